// round 2
// baseline (speedup 1.0000x reference)
#include <cuda_runtime.h>
#include <cstdint>

// ---------------- problem constants ----------------
#define BB   32
#define SS   256
#define TT   128
#define EENC 512
#define HH   512
#define EEMB 256
#define VV   32000
#define K0   1280   // emb(256)+context(512)+h0(512)
#define K1   1024   // h0(512)+h1(512)
#define KL   1024   // h1(512)+context(512)
#define OUT_TAIL_OFF 131072000ll // B*T*V

// ---------------- device scratch ----------------
__device__ float g_keyproj[BB*SS*HH];        // 16.8 MB
__device__ float g_Wcat0[2048*K0];           // 10.5 MB
__device__ float g_Wcat1[2048*K1];           // 8.4 MB
__device__ float g_bcat0[2048];
__device__ float g_bcat1[2048];
__device__ float g_xcat0[BB*K0];             // [emb | ctx | h0]
__device__ float g_xcat1[BB*K1];             // [h0 | h1]
__device__ float g_gates[BB*2048];
__device__ float g_h1[BB*HH];
__device__ float g_c0[BB*HH];
__device__ float g_c1[BB*HH];
__device__ float g_Xall[BB*TT*KL];           // 16.8 MB, row = b*T+t : [h1 | ctx]

// ---------------- math helpers ----------------
__device__ __forceinline__ float tanh_acc(float x){
    float xx = fminf(15.f, fmaxf(-15.f, x));
    float e  = __expf(2.f*xx);
    return 1.f - __fdividef(2.f, e + 1.f);
}
__device__ __forceinline__ float sigf(float x){
    float xx = fminf(30.f, fmaxf(-30.f, x));
    return __fdividef(1.f, 1.f + __expf(-xx));
}

// ---------------- init: build concat weights, zero state ----------------
__global__ void init_kernel(const float* __restrict__ Wih0, const float* __restrict__ Whh0,
                            const float* __restrict__ bih0, const float* __restrict__ bhh0,
                            const float* __restrict__ Wih1, const float* __restrict__ Whh1,
                            const float* __restrict__ bih1, const float* __restrict__ bhh1)
{
    const int NW0 = 2048*K0;          // 2,621,440
    const int NW1 = 2048*K1;          // 2,097,152
    const int NB  = 2048;
    const int NZ  = BB*HH*3 + BB*K0 + BB*K1; // h1,c0,c1 + xcat0 + xcat1
    const int TOT = NW0 + NW1 + 2*NB + NZ;
    for (int idx = blockIdx.x*blockDim.x + threadIdx.x; idx < TOT; idx += gridDim.x*blockDim.x){
        int r = idx;
        if (r < NW0){
            int j = r / K0, k = r % K0;
            g_Wcat0[r] = (k < 768) ? Wih0[j*768 + k] : Whh0[j*512 + (k-768)];
            continue;
        }
        r -= NW0;
        if (r < NW1){
            int j = r / K1, k = r % K1;
            g_Wcat1[r] = (k < 512) ? Wih1[j*512 + k] : Whh1[j*512 + (k-512)];
            continue;
        }
        r -= NW1;
        if (r < NB){ g_bcat0[r] = bih0[r] + bhh0[r]; continue; }
        r -= NB;
        if (r < NB){ g_bcat1[r] = bih1[r] + bhh1[r]; continue; }
        r -= NB;
        if (r < BB*HH){ g_h1[r] = 0.f; continue; }
        r -= BB*HH;
        if (r < BB*HH){ g_c0[r] = 0.f; continue; }
        r -= BB*HH;
        if (r < BB*HH){ g_c1[r] = 0.f; continue; }
        r -= BB*HH;
        if (r < BB*K0){ g_xcat0[r] = 0.f; continue; }
        r -= BB*K0;
        g_xcat1[r] = 0.f;
    }
}

// ---------------- generic TN GEMM: C[m][n] = sum_k A[m][k]*B[n][k] + bias[n] ----------------
template<int BM,int BN,int BK,int TM,int TN,int THREADS>
__global__ __launch_bounds__(THREADS) void gemm_tn(
    const float* __restrict__ A, const float* __restrict__ B,
    const float* __restrict__ bias, float* __restrict__ C,
    int M, int N, int K)
{
    constexpr int AF4 = BM*BK/(4*THREADS);
    constexpr int BF4 = BN*BK/(4*THREADS);
    constexpr int KC4 = BK/4;
    constexpr int NT  = BN/TN;
    static_assert((BM/TM)*(BN/TN) == THREADS, "thread shape");
    static_assert(AF4 >= 1 && BF4 >= 1, "load shape");

    __shared__ float As[2][BK][BM];
    __shared__ float Bs[2][BK][BN];

    const int tid = threadIdx.x;
    const int tm  = (tid / NT) * TM;
    const int tn  = (tid % NT) * TN;
    const size_t m0 = (size_t)blockIdx.y * BM;
    const size_t n0 = (size_t)blockIdx.x * BN;
    const float* Ab = A + m0 * K;
    const float* Bb = B + n0 * K;

    float acc[TM][TN];
#pragma unroll
    for (int i=0;i<TM;i++)
#pragma unroll
        for (int j=0;j<TN;j++) acc[i][j] = 0.f;

    float4 ra[AF4], rb[BF4];

    // prologue: load tile 0
#pragma unroll
    for (int i=0;i<AF4;i++){
        int f = tid + i*THREADS; int r = f/KC4, c = f%KC4;
        ra[i] = *reinterpret_cast<const float4*>(Ab + (size_t)r*K + c*4);
    }
#pragma unroll
    for (int i=0;i<BF4;i++){
        int f = tid + i*THREADS; int r = f/KC4, c = f%KC4;
        rb[i] = *reinterpret_cast<const float4*>(Bb + (size_t)r*K + c*4);
    }
#pragma unroll
    for (int i=0;i<AF4;i++){
        int f = tid + i*THREADS; int r = f/KC4, c = f%KC4;
        As[0][c*4+0][r]=ra[i].x; As[0][c*4+1][r]=ra[i].y;
        As[0][c*4+2][r]=ra[i].z; As[0][c*4+3][r]=ra[i].w;
    }
#pragma unroll
    for (int i=0;i<BF4;i++){
        int f = tid + i*THREADS; int r = f/KC4, c = f%KC4;
        Bs[0][c*4+0][r]=rb[i].x; Bs[0][c*4+1][r]=rb[i].y;
        Bs[0][c*4+2][r]=rb[i].z; Bs[0][c*4+3][r]=rb[i].w;
    }
    __syncthreads();

    const int KT = K / BK;
    for (int kt = 0; kt < KT; ++kt){
        const int cur = kt & 1;
        const bool nx = (kt + 1 < KT);
        if (nx){
            const float* Ab2 = Ab + (size_t)(kt+1)*BK;
            const float* Bb2 = Bb + (size_t)(kt+1)*BK;
#pragma unroll
            for (int i=0;i<AF4;i++){
                int f = tid + i*THREADS; int r = f/KC4, c = f%KC4;
                ra[i] = *reinterpret_cast<const float4*>(Ab2 + (size_t)r*K + c*4);
            }
#pragma unroll
            for (int i=0;i<BF4;i++){
                int f = tid + i*THREADS; int r = f/KC4, c = f%KC4;
                rb[i] = *reinterpret_cast<const float4*>(Bb2 + (size_t)r*K + c*4);
            }
        }
#pragma unroll
        for (int k=0;k<BK;k++){
            float a[TM], b[TN];
            if constexpr (TM % 4 == 0){
#pragma unroll
                for (int i=0;i<TM/4;i++){
                    float4 t = *reinterpret_cast<const float4*>(&As[cur][k][tm + i*4]);
                    a[i*4]=t.x; a[i*4+1]=t.y; a[i*4+2]=t.z; a[i*4+3]=t.w;
                }
            } else {
#pragma unroll
                for (int i=0;i<TM;i++) a[i] = As[cur][k][tm+i];
            }
            if constexpr (TN % 4 == 0){
#pragma unroll
                for (int j=0;j<TN/4;j++){
                    float4 t = *reinterpret_cast<const float4*>(&Bs[cur][k][tn + j*4]);
                    b[j*4]=t.x; b[j*4+1]=t.y; b[j*4+2]=t.z; b[j*4+3]=t.w;
                }
            } else {
#pragma unroll
                for (int j=0;j<TN;j++) b[j] = Bs[cur][k][tn+j];
            }
#pragma unroll
            for (int i=0;i<TM;i++)
#pragma unroll
                for (int j=0;j<TN;j++) acc[i][j] = fmaf(a[i], b[j], acc[i][j]);
        }
        if (nx){
            const int nb = cur ^ 1;
#pragma unroll
            for (int i=0;i<AF4;i++){
                int f = tid + i*THREADS; int r = f/KC4, c = f%KC4;
                As[nb][c*4+0][r]=ra[i].x; As[nb][c*4+1][r]=ra[i].y;
                As[nb][c*4+2][r]=ra[i].z; As[nb][c*4+3][r]=ra[i].w;
            }
#pragma unroll
            for (int i=0;i<BF4;i++){
                int f = tid + i*THREADS; int r = f/KC4, c = f%KC4;
                Bs[nb][c*4+0][r]=rb[i].x; Bs[nb][c*4+1][r]=rb[i].y;
                Bs[nb][c*4+2][r]=rb[i].z; Bs[nb][c*4+3][r]=rb[i].w;
            }
            __syncthreads();
        }
    }
    // epilogue
#pragma unroll
    for (int i=0;i<TM;i++){
#pragma unroll
        for (int j=0;j<TN;j++){
            size_t cn = n0 + tn + j;
            C[(m0 + tm + i)*(size_t)N + cn] = acc[i][j] + bias[cn];
        }
    }
}

// ---------------- attention + emb gather (one block per batch) ----------------
__global__ __launch_bounds__(256) void attn_kernel(
    const float* __restrict__ enc, const int* __restrict__ tok,
    const float* __restrict__ emb, const float* __restrict__ Wq,
    const float* __restrict__ bq,  const float* __restrict__ v, int t)
{
    const int b = blockIdx.x, tid = threadIdx.x;
    const int w = tid >> 5, lane = tid & 31;
    __shared__ float h1s[HH], qp[HH], vs[HH], sc[SS];
    __shared__ float red[8];
    __shared__ float smax_s, sinv_s;

    for (int i = tid; i < HH; i += 256){ h1s[i] = g_h1[b*HH + i]; vs[i] = v[i]; }
    __syncthreads();

    // qproj[h] = bq[h] + sum_k Wq[h][k]*h1[k]  (warp per 64 outputs)
    for (int hh = 0; hh < 64; ++hh){
        int h = w*64 + hh;
        const float* wr = Wq + (size_t)h*HH;
        float p = 0.f;
#pragma unroll
        for (int i = 0; i < 16; i++) p = fmaf(wr[i*32 + lane], h1s[i*32 + lane], p);
#pragma unroll
        for (int o = 16; o; o >>= 1) p += __shfl_xor_sync(0xffffffffu, p, o);
        if (lane == 0) qp[h] = p + bq[h];
    }
    // emb gather into xcat0[:, 0:256]
    {
        int row = tok[b*TT + t];
        if (tid < 256) g_xcat0[b*K0 + tid] = emb[(size_t)row*EEMB + tid];
    }
    __syncthreads();

    // scores[s] = sum_h v[h]*tanh(kp[b,s,h] + qp[h])
    {
        const int s = tid;
        const float* kp = g_keyproj + ((size_t)(b*SS + s))*HH;
        float acc = 0.f;
#pragma unroll 2
        for (int h = 0; h < HH; h += 4){
            float4 k4 = *reinterpret_cast<const float4*>(kp + h);
            acc = fmaf(vs[h+0], tanh_acc(k4.x + qp[h+0]), acc);
            acc = fmaf(vs[h+1], tanh_acc(k4.y + qp[h+1]), acc);
            acc = fmaf(vs[h+2], tanh_acc(k4.z + qp[h+2]), acc);
            acc = fmaf(vs[h+3], tanh_acc(k4.w + qp[h+3]), acc);
        }
        sc[s] = acc;
    }
    __syncthreads();

    // softmax over 256
    float x = sc[tid];
    float m = x;
#pragma unroll
    for (int o = 16; o; o >>= 1) m = fmaxf(m, __shfl_xor_sync(0xffffffffu, m, o));
    if (lane == 0) red[w] = m;
    __syncthreads();
    if (tid == 0){
        float mm = red[0];
#pragma unroll
        for (int i = 1; i < 8; i++) mm = fmaxf(mm, red[i]);
        smax_s = mm;
    }
    __syncthreads();
    float ex = __expf(x - smax_s);
    float s2 = ex;
#pragma unroll
    for (int o = 16; o; o >>= 1) s2 += __shfl_xor_sync(0xffffffffu, s2, o);
    if (lane == 0) red[w] = s2;
    __syncthreads();
    if (tid == 0){
        float ss = 0.f;
#pragma unroll
        for (int i = 0; i < 8; i++) ss += red[i];
        sinv_s = 1.f / ss;
    }
    __syncthreads();
    sc[tid] = ex * sinv_s;
    __syncthreads();

    // context[e] = sum_s w[s]*enc[b,s,e]  -> xcat0[:,256:768] and Xall[:,512:1024]
    for (int e0 = tid; e0 < EENC; e0 += 256){
        float acc = 0.f;
        const float* eb = enc + ((size_t)b*SS)*EENC + e0;
#pragma unroll 4
        for (int s = 0; s < SS; s++) acc = fmaf(sc[s], eb[(size_t)s*EENC], acc);
        g_xcat0[b*K0 + 256 + e0] = acc;
        g_Xall[((size_t)(b*TT + t))*KL + 512 + e0] = acc;
    }
}

// ---------------- LSTM cell elementwise ----------------
__global__ __launch_bounds__(512) void cell0_kernel()
{
    const int b = blockIdx.x, u = threadIdx.x;
    const float* g = g_gates + b*2048;
    float gi = g[u], gf = g[512+u], gg = g[1024+u], go = g[1536+u];
    float c = sigf(gf)*g_c0[b*HH + u] + sigf(gi)*tanh_acc(gg);
    float h = sigf(go)*tanh_acc(c);
    g_c0[b*HH + u] = c;
    g_xcat0[b*K0 + 768 + u] = h;   // h0 for next step's gates0
    g_xcat1[b*K1 + u]       = h;   // h0 input to gates1 (this step)
}

__global__ __launch_bounds__(512) void cell1_kernel(int t)
{
    const int b = blockIdx.x, u = threadIdx.x;
    const float* g = g_gates + b*2048;
    float gi = g[u], gf = g[512+u], gg = g[1024+u], go = g[1536+u];
    float c = sigf(gf)*g_c1[b*HH + u] + sigf(gi)*tanh_acc(gg);
    float h = sigf(go)*tanh_acc(c);
    g_c1[b*HH + u] = c;
    g_h1[b*HH + u] = h;                       // query for next step's attention
    g_xcat1[b*K1 + 512 + u] = h;              // h1 input to next step's gates1
    g_Xall[((size_t)(b*TT + t))*KL + u] = h;  // logits input row
}

// ---------------- tail: final h,c states ----------------
__global__ __launch_bounds__(512) void tail_kernel(float* __restrict__ out)
{
    int idx = blockIdx.x*blockDim.x + threadIdx.x;   // 65536 total
    int part = idx / (BB*HH);
    int off  = idx % (BB*HH);
    int b = off / HH, u = off % HH;
    float val;
    if      (part == 0) val = g_xcat1[b*K1 + u];   // h0 final
    else if (part == 1) val = g_h1[off];           // h1 final
    else if (part == 2) val = g_c0[off];           // c0 final
    else                val = g_c1[off];           // c1 final
    out[OUT_TAIL_OFF + idx] = val;
}

// ---------------- launch ----------------
extern "C" void kernel_launch(void* const* d_in, const int* in_sizes, int n_in,
                              void* d_out, int out_size)
{
    const float* enc  = (const float*)d_in[0];
    const int*   tok  = (const int*)  d_in[1];
    const float* emb  = (const float*)d_in[2];
    const float* Wq   = (const float*)d_in[3];
    const float* bq   = (const float*)d_in[4];
    const float* Wk   = (const float*)d_in[5];
    const float* bk   = (const float*)d_in[6];
    const float* v    = (const float*)d_in[7];
    const float* Wih0 = (const float*)d_in[8];
    const float* Whh0 = (const float*)d_in[9];
    const float* bih0 = (const float*)d_in[10];
    const float* bhh0 = (const float*)d_in[11];
    const float* Wih1 = (const float*)d_in[12];
    const float* Whh1 = (const float*)d_in[13];
    const float* bih1 = (const float*)d_in[14];
    const float* bhh1 = (const float*)d_in[15];
    const float* Wout = (const float*)d_in[16];
    const float* bout = (const float*)d_in[17];
    float* out = (float*)d_out;

    float *p_keyproj, *p_Wcat0, *p_bcat0, *p_Wcat1, *p_bcat1;
    float *p_xcat0, *p_xcat1, *p_gates, *p_Xall;
    cudaGetSymbolAddress((void**)&p_keyproj, g_keyproj);
    cudaGetSymbolAddress((void**)&p_Wcat0,  g_Wcat0);
    cudaGetSymbolAddress((void**)&p_bcat0,  g_bcat0);
    cudaGetSymbolAddress((void**)&p_Wcat1,  g_Wcat1);
    cudaGetSymbolAddress((void**)&p_bcat1,  g_bcat1);
    cudaGetSymbolAddress((void**)&p_xcat0,  g_xcat0);
    cudaGetSymbolAddress((void**)&p_xcat1,  g_xcat1);
    cudaGetSymbolAddress((void**)&p_gates,  g_gates);
    cudaGetSymbolAddress((void**)&p_Xall,   g_Xall);

    // init concat weights + zero state
    init_kernel<<<2048, 256>>>(Wih0, Whh0, bih0, bhh0, Wih1, Whh1, bih1, bhh1);

    // key_proj = enc(8192x512) @ Wk^T(512x512) + bk
    {
        dim3 grid(HH/64, (BB*SS)/64);
        gemm_tn<64,64,16,4,4,256><<<grid, 256>>>(enc, Wk, bk, p_keyproj, BB*SS, HH, EENC);
    }

    // sequential decode: recurrence only (logits deferred)
    for (int t = 0; t < TT; ++t){
        attn_kernel<<<BB, 256>>>(enc, tok, emb, Wq, bq, v, t);
        {
            dim3 grid(2048/16, 1);
            gemm_tn<32,16,32,2,2,128><<<grid, 128>>>(p_xcat0, p_Wcat0, p_bcat0, p_gates, BB, 2048, K0);
        }
        cell0_kernel<<<BB, 512>>>();
        {
            dim3 grid(2048/16, 1);
            gemm_tn<32,16,32,2,2,128><<<grid, 128>>>(p_xcat1, p_Wcat1, p_bcat1, p_gates, BB, 2048, K1);
        }
        cell1_kernel<<<BB, 512>>>(t);
    }

    // phase 2: all logits at once: Xall(4096x1024) @ Wout^T(32000x1024) + bout -> out
    {
        dim3 grid(VV/64, (BB*TT)/128);
        gemm_tn<128,64,16,8,8,128><<<grid, 128>>>(p_Xall, Wout, bout, out, BB*TT, VV, KL);
    }

    // final h, c
    tail_kernel<<<128, 512>>>(out);
}

// round 3
// speedup vs baseline: 2.1869x; 2.1869x over previous
#include <cuda_runtime.h>
#include <cstdint>

#define BB 32
#define SS 256
#define TT 128
#define EENC 512
#define HH 512
#define EEMB 256
#define VV 32000
#define K0 1280
#define K1 1024
#define KL 1024
#define OUT_TAIL_OFF 131072000ll

__device__ float g_keyproj[BB*SS*HH];
__device__ float g_Wcat0[2048*K0];
__device__ float g_Wcat1[2048*K1];
__device__ float g_bcat0[2048];
__device__ float g_bcat1[2048];
__device__ float g_Wqt[HH*HH];
__device__ float g_Wt32[(size_t)VV*KL];
__device__ float g_xcat0[BB*K0];
__device__ float g_xcat1[BB*K1];
__device__ float g_part0[10*BB*2048];
__device__ float g_part1[8*BB*2048];
__device__ float g_h1[BB*HH];
__device__ float g_c0[BB*HH];
__device__ float g_c1[BB*HH];
__device__ float g_qp[BB*HH];
__device__ float g_scores[BB*SS];
__device__ float g_Xall[(size_t)BB*TT*KL];

__device__ __forceinline__ float tanh_acc(float x){
    float xx = fminf(15.f, fmaxf(-15.f, x));
    float e  = __expf(2.f*xx);
    return 1.f - __fdividef(2.f, e + 1.f);
}
__device__ __forceinline__ float sigf(float x){
    float xx = fminf(30.f, fmaxf(-30.f, x));
    return __fdividef(1.f, 1.f + __expf(-xx));
}
__device__ __forceinline__ float tf32r(float x){
    unsigned u; asm("cvt.rna.tf32.f32 %0, %1;" : "=r"(u) : "f"(x));
    return __uint_as_float(u);
}

__global__ void init_kernel(const float* __restrict__ Wih0, const float* __restrict__ Whh0,
                            const float* __restrict__ bih0, const float* __restrict__ bhh0,
                            const float* __restrict__ Wih1, const float* __restrict__ Whh1,
                            const float* __restrict__ bih1, const float* __restrict__ bhh1,
                            const float* __restrict__ Wq,   const float* __restrict__ bq)
{
    const int NW0=2048*K0, NW1=2048*K1, NB=2048, NWQ=HH*HH, NQP=BB*HH;
    const int NZ = BB*HH*3 + BB*K0 + BB*K1;
    const int TOT = NW0+NW1+2*NB+NWQ+NQP+NZ;
    for (int idx = blockIdx.x*blockDim.x+threadIdx.x; idx < TOT; idx += gridDim.x*blockDim.x){
        int r = idx;
        if (r < NW0){ int j=r/K0,k=r%K0; g_Wcat0[r]=(k<768)?Wih0[j*768+k]:Whh0[j*512+(k-768)]; continue; }
        r -= NW0;
        if (r < NW1){ int j=r/K1,k=r%K1; g_Wcat1[r]=(k<512)?Wih1[j*512+k]:Whh1[j*512+(k-512)]; continue; }
        r -= NW1;
        if (r < NB){ g_bcat0[r]=bih0[r]+bhh0[r]; continue; }
        r -= NB;
        if (r < NB){ g_bcat1[r]=bih1[r]+bhh1[r]; continue; }
        r -= NB;
        if (r < NWQ){ int k=r/HH,h=r%HH; g_Wqt[r]=Wq[h*HH+k]; continue; }
        r -= NWQ;
        if (r < NQP){ g_qp[r]=bq[r%HH]; continue; }
        r -= NQP;
        if (r < BB*HH){ g_h1[r]=0.f; continue; }
        r -= BB*HH;
        if (r < BB*HH){ g_c0[r]=0.f; continue; }
        r -= BB*HH;
        if (r < BB*HH){ g_c1[r]=0.f; continue; }
        r -= BB*HH;
        if (r < BB*K0){ g_xcat0[r]=0.f; continue; }
        r -= BB*K0;
        g_xcat1[r]=0.f;
    }
}

__global__ void cvt_wout(const float* __restrict__ Wout)
{
    size_t n = (size_t)VV*KL/4;
    for (size_t i = blockIdx.x*blockDim.x+threadIdx.x; i < n; i += (size_t)gridDim.x*blockDim.x){
        float4 v = reinterpret_cast<const float4*>(Wout)[i];
        v.x=tf32r(v.x); v.y=tf32r(v.y); v.z=tf32r(v.z); v.w=tf32r(v.w);
        reinterpret_cast<float4*>(g_Wt32)[i] = v;
    }
}

// fp32 GEMM for keyproj: C = A@B^T + bias
template<int BM,int BN,int BK,int TM,int TN,int THREADS>
__global__ __launch_bounds__(THREADS) void gemm_tn(
    const float* __restrict__ A, const float* __restrict__ B,
    const float* __restrict__ bias, float* __restrict__ C, int M, int N, int K)
{
    constexpr int AF4 = BM*BK/(4*THREADS);
    constexpr int BF4 = BN*BK/(4*THREADS);
    constexpr int KC4 = BK/4;
    constexpr int NT  = BN/TN;
    __shared__ float As[2][BK][BM];
    __shared__ float Bs[2][BK][BN];
    const int tid = threadIdx.x;
    const int tm = (tid/NT)*TM, tn = (tid%NT)*TN;
    const size_t m0 = (size_t)blockIdx.y*BM, n0 = (size_t)blockIdx.x*BN;
    const float* Ab = A + m0*K;
    const float* Bb = B + n0*K;
    float acc[TM][TN];
#pragma unroll
    for (int i=0;i<TM;i++)
#pragma unroll
        for (int j=0;j<TN;j++) acc[i][j]=0.f;
    float4 ra[AF4], rb[BF4];
#pragma unroll
    for (int i=0;i<AF4;i++){ int f=tid+i*THREADS,r=f/KC4,c=f%KC4;
        ra[i]=*reinterpret_cast<const float4*>(Ab+(size_t)r*K+c*4); }
#pragma unroll
    for (int i=0;i<BF4;i++){ int f=tid+i*THREADS,r=f/KC4,c=f%KC4;
        rb[i]=*reinterpret_cast<const float4*>(Bb+(size_t)r*K+c*4); }
#pragma unroll
    for (int i=0;i<AF4;i++){ int f=tid+i*THREADS,r=f/KC4,c=f%KC4;
        As[0][c*4+0][r]=ra[i].x; As[0][c*4+1][r]=ra[i].y; As[0][c*4+2][r]=ra[i].z; As[0][c*4+3][r]=ra[i].w; }
#pragma unroll
    for (int i=0;i<BF4;i++){ int f=tid+i*THREADS,r=f/KC4,c=f%KC4;
        Bs[0][c*4+0][r]=rb[i].x; Bs[0][c*4+1][r]=rb[i].y; Bs[0][c*4+2][r]=rb[i].z; Bs[0][c*4+3][r]=rb[i].w; }
    __syncthreads();
    const int KT = K/BK;
    for (int kt=0; kt<KT; ++kt){
        const int cur = kt&1;
        const bool nx = (kt+1<KT);
        if (nx){
            const float* A2 = Ab+(size_t)(kt+1)*BK;
            const float* B2 = Bb+(size_t)(kt+1)*BK;
#pragma unroll
            for (int i=0;i<AF4;i++){ int f=tid+i*THREADS,r=f/KC4,c=f%KC4;
                ra[i]=*reinterpret_cast<const float4*>(A2+(size_t)r*K+c*4); }
#pragma unroll
            for (int i=0;i<BF4;i++){ int f=tid+i*THREADS,r=f/KC4,c=f%KC4;
                rb[i]=*reinterpret_cast<const float4*>(B2+(size_t)r*K+c*4); }
        }
#pragma unroll
        for (int k=0;k<BK;k++){
            float a[TM], b[TN];
#pragma unroll
            for (int i=0;i<TM/4;i++){ float4 t=*reinterpret_cast<const float4*>(&As[cur][k][tm+i*4]);
                a[i*4]=t.x;a[i*4+1]=t.y;a[i*4+2]=t.z;a[i*4+3]=t.w; }
#pragma unroll
            for (int j=0;j<TN/4;j++){ float4 t=*reinterpret_cast<const float4*>(&Bs[cur][k][tn+j*4]);
                b[j*4]=t.x;b[j*4+1]=t.y;b[j*4+2]=t.z;b[j*4+3]=t.w; }
#pragma unroll
            for (int i=0;i<TM;i++)
#pragma unroll
                for (int j=0;j<TN;j++) acc[i][j]=fmaf(a[i],b[j],acc[i][j]);
        }
        if (nx){
            const int nb = cur^1;
#pragma unroll
            for (int i=0;i<AF4;i++){ int f=tid+i*THREADS,r=f/KC4,c=f%KC4;
                As[nb][c*4+0][r]=ra[i].x; As[nb][c*4+1][r]=ra[i].y; As[nb][c*4+2][r]=ra[i].z; As[nb][c*4+3][r]=ra[i].w; }
#pragma unroll
            for (int i=0;i<BF4;i++){ int f=tid+i*THREADS,r=f/KC4,c=f%KC4;
                Bs[nb][c*4+0][r]=rb[i].x; Bs[nb][c*4+1][r]=rb[i].y; Bs[nb][c*4+2][r]=rb[i].z; Bs[nb][c*4+3][r]=rb[i].w; }
            __syncthreads();
        }
    }
#pragma unroll
    for (int i=0;i<TM;i++)
#pragma unroll
        for (int j=0;j<TN;j++){
            size_t cn = n0+tn+j;
            C[(m0+tm+i)*(size_t)N+cn] = acc[i][j] + bias[cn];
        }
}

// gates split-K: partials Cp[split][32][2048]
__global__ __launch_bounds__(256) void gates_gemm(
    const float* __restrict__ X, const float* __restrict__ W,
    float* __restrict__ Cp, int K)
{
    __shared__ float As[2][16][32];
    __shared__ float Bs[2][16][132];
    const int tid = threadIdx.x;
    const int j0 = blockIdx.x*128;
    const int k0 = blockIdx.y*128;
    const int tm = (tid>>5)*4, tn = (tid&31)*4;
    float acc[4][4] = {};
    float4 ra; float4 rb[2];
    if (tid < 128){ int r=tid>>2,c=tid&3;
        ra = *reinterpret_cast<const float4*>(X+(size_t)r*K+k0+c*4); }
#pragma unroll
    for (int i=0;i<2;i++){ int f=tid+i*256,r=f>>2,c=f&3;
        rb[i] = *reinterpret_cast<const float4*>(W+(size_t)(j0+r)*K+k0+c*4); }
    if (tid < 128){ int r=tid>>2,c=tid&3;
        As[0][c*4+0][r]=ra.x; As[0][c*4+1][r]=ra.y; As[0][c*4+2][r]=ra.z; As[0][c*4+3][r]=ra.w; }
#pragma unroll
    for (int i=0;i<2;i++){ int f=tid+i*256,r=f>>2,c=f&3;
        Bs[0][c*4+0][r]=rb[i].x; Bs[0][c*4+1][r]=rb[i].y; Bs[0][c*4+2][r]=rb[i].z; Bs[0][c*4+3][r]=rb[i].w; }
    __syncthreads();
    for (int kt=0; kt<8; ++kt){
        const int buf = kt&1;
        const bool nx = (kt<7);
        if (nx){
            int kk = k0 + (kt+1)*16;
            if (tid < 128){ int r=tid>>2,c=tid&3;
                ra = *reinterpret_cast<const float4*>(X+(size_t)r*K+kk+c*4); }
#pragma unroll
            for (int i=0;i<2;i++){ int f=tid+i*256,r=f>>2,c=f&3;
                rb[i] = *reinterpret_cast<const float4*>(W+(size_t)(j0+r)*K+kk+c*4); }
        }
#pragma unroll
        for (int k=0;k<16;k++){
            float4 a = *reinterpret_cast<const float4*>(&As[buf][k][tm]);
            float4 b = *reinterpret_cast<const float4*>(&Bs[buf][k][tn]);
            float av[4]={a.x,a.y,a.z,a.w}, bv[4]={b.x,b.y,b.z,b.w};
#pragma unroll
            for (int i=0;i<4;i++)
#pragma unroll
                for (int j=0;j<4;j++) acc[i][j]=fmaf(av[i],bv[j],acc[i][j]);
        }
        if (nx){
            const int nb = buf^1;
            if (tid < 128){ int r=tid>>2,c=tid&3;
                As[nb][c*4+0][r]=ra.x; As[nb][c*4+1][r]=ra.y; As[nb][c*4+2][r]=ra.z; As[nb][c*4+3][r]=ra.w; }
#pragma unroll
            for (int i=0;i<2;i++){ int f=tid+i*256,r=f>>2,c=f&3;
                Bs[nb][c*4+0][r]=rb[i].x; Bs[nb][c*4+1][r]=rb[i].y; Bs[nb][c*4+2][r]=rb[i].z; Bs[nb][c*4+3][r]=rb[i].w; }
            __syncthreads();
        }
    }
    float* out = Cp + blockIdx.y*65536;
#pragma unroll
    for (int i=0;i<4;i++)
#pragma unroll
        for (int j=0;j<4;j++)
            out[(tm+i)*2048 + j0+tn+j] = acc[i][j];
}

__global__ __launch_bounds__(512) void cell0_kernel()
{
    const int b = blockIdx.x, u = threadIdx.x;
    float gi=g_bcat0[u], gf=g_bcat0[512+u], gg=g_bcat0[1024+u], go=g_bcat0[1536+u];
#pragma unroll
    for (int s=0;s<10;s++){
        const float* p = g_part0 + s*65536 + b*2048;
        gi += p[u]; gf += p[512+u]; gg += p[1024+u]; go += p[1536+u];
    }
    float c = sigf(gf)*g_c0[b*HH+u] + sigf(gi)*tanh_acc(gg);
    float h = sigf(go)*tanh_acc(c);
    g_c0[b*HH+u] = c;
    g_xcat0[b*K0 + 768 + u] = h;
    g_xcat1[b*K1 + u]       = h;
}

__global__ __launch_bounds__(512) void cell1_kernel(const float* __restrict__ bq, int t)
{
    const int b = blockIdx.x, u = threadIdx.x;
    __shared__ float h1s[512];
    __shared__ float qpart[4][512];
    float gi=g_bcat1[u], gf=g_bcat1[512+u], gg=g_bcat1[1024+u], go=g_bcat1[1536+u];
#pragma unroll
    for (int s=0;s<8;s++){
        const float* p = g_part1 + s*65536 + b*2048;
        gi += p[u]; gf += p[512+u]; gg += p[1024+u]; go += p[1536+u];
    }
    float c = sigf(gf)*g_c1[b*HH+u] + sigf(gi)*tanh_acc(gg);
    float h = sigf(go)*tanh_acc(c);
    g_c1[b*HH+u] = c;
    g_h1[b*HH+u] = h;
    g_xcat1[b*K1 + 512 + u] = h;
    g_Xall[((size_t)(b*TT+t))*KL + u] = tf32r(h);
    h1s[u] = h;
    __syncthreads();
    // qproj for next step: qp = Wq@h1 + bq, Wqt is [k][h]
    const int h4 = (u & 127)*4, kp = u >> 7;
    float4 a = make_float4(0.f,0.f,0.f,0.f);
    const float* wb = g_Wqt + (size_t)kp*128*HH + h4;
#pragma unroll 4
    for (int k=0;k<128;k++){
        float4 w4 = *reinterpret_cast<const float4*>(wb + (size_t)k*HH);
        float xv = h1s[kp*128 + k];
        a.x=fmaf(w4.x,xv,a.x); a.y=fmaf(w4.y,xv,a.y); a.z=fmaf(w4.z,xv,a.z); a.w=fmaf(w4.w,xv,a.w);
    }
    *reinterpret_cast<float4*>(&qpart[kp][h4]) = a;
    __syncthreads();
    g_qp[b*HH+u] = qpart[0][u]+qpart[1][u]+qpart[2][u]+qpart[3][u] + bq[u];
}

__global__ __launch_bounds__(256) void scores_kernel(const float* __restrict__ v)
{
    const int b = blockIdx.x, tid = threadIdx.x;
    __shared__ float qs[512], vsm[512];
    qs[tid] = g_qp[b*HH+tid];  qs[tid+256] = g_qp[b*HH+tid+256];
    vsm[tid] = v[tid];         vsm[tid+256] = v[tid+256];
    __syncthreads();
    const int sl = tid>>3, part = tid&7;
    const int s = blockIdx.y*32 + sl;
    const float* kp = g_keyproj + ((size_t)(b*SS+s))*HH + part*64;
    const float* qq = qs + part*64;
    const float* vv = vsm + part*64;
    float acc = 0.f;
#pragma unroll
    for (int i=0;i<16;i++){
        float4 k4 = *reinterpret_cast<const float4*>(kp + i*4);
        acc = fmaf(vv[i*4+0], tanh_acc(k4.x+qq[i*4+0]), acc);
        acc = fmaf(vv[i*4+1], tanh_acc(k4.y+qq[i*4+1]), acc);
        acc = fmaf(vv[i*4+2], tanh_acc(k4.z+qq[i*4+2]), acc);
        acc = fmaf(vv[i*4+3], tanh_acc(k4.w+qq[i*4+3]), acc);
    }
    acc += __shfl_down_sync(0xffffffffu, acc, 4);
    acc += __shfl_down_sync(0xffffffffu, acc, 2);
    acc += __shfl_down_sync(0xffffffffu, acc, 1);
    if (part == 0) g_scores[b*SS+s] = acc;
}

__global__ __launch_bounds__(256) void smctx_kernel(
    const float* __restrict__ enc, const int* __restrict__ tok,
    const float* __restrict__ emb, int t)
{
    const int b = blockIdx.x, tid = threadIdx.x;
    const int w = tid>>5, lane = tid&31;
    __shared__ float wsm[SS];
    __shared__ float red[8];
    __shared__ float smax_s, sinv_s;
    float x = g_scores[b*SS+tid];
    float m = x;
#pragma unroll
    for (int o=16;o;o>>=1) m = fmaxf(m, __shfl_xor_sync(0xffffffffu, m, o));
    if (lane==0) red[w]=m;
    __syncthreads();
    if (tid==0){ float mm=red[0];
#pragma unroll
        for (int i=1;i<8;i++) mm=fmaxf(mm,red[i]); smax_s=mm; }
    __syncthreads();
    float ex = __expf(x - smax_s);
    float s2 = ex;
#pragma unroll
    for (int o=16;o;o>>=1) s2 += __shfl_xor_sync(0xffffffffu, s2, o);
    if (lane==0) red[w]=s2;
    __syncthreads();
    if (tid==0){ float ss=0.f;
#pragma unroll
        for (int i=0;i<8;i++) ss+=red[i]; sinv_s=1.f/ss; }
    __syncthreads();
    wsm[tid] = ex*sinv_s;
    { int row = tok[b*TT+t]; g_xcat0[b*K0+tid] = emb[(size_t)row*EEMB+tid]; }
    __syncthreads();
#pragma unroll
    for (int e0=0;e0<2;e0++){
        int e = tid + e0*256;
        float acc = 0.f;
        const float* eb = enc + ((size_t)b*SS)*EENC + e;
#pragma unroll 4
        for (int s=0;s<SS;s++) acc = fmaf(wsm[s], eb[(size_t)s*EENC], acc);
        g_xcat0[b*K0 + 256 + e] = acc;
        g_Xall[((size_t)(b*TT+t))*KL + 512 + e] = tf32r(acc);
    }
}

// logits: tf32 mma.sync, BM128 x BN64 x BK16, 8 warps
__global__ __launch_bounds__(256) void logits_mma(
    const float* __restrict__ A, const float* __restrict__ B,
    const float* __restrict__ bias, float* __restrict__ C)
{
    __shared__ float As[2][128][20];
    __shared__ float Bs[2][64][20];
    const int tid = threadIdx.x, lane = tid&31, w = tid>>5;
    const int wm = (w&3)*32, wn = (w>>2)*32;
    const int m0 = blockIdx.y*128, n0 = blockIdx.x*64;
    const int lr = lane>>2, lc = lane&3;
    float d[2][4][4] = {};

#define STAGE(bufi, kt) do { \
    int kk = (kt)*16; \
    _Pragma("unroll") \
    for (int i=0;i<2;i++){ \
        int f = tid + i*256; int r = f>>2, c = f&3; \
        unsigned dst = (unsigned)__cvta_generic_to_shared(&As[bufi][r][c*4]); \
        const float* src = A + (size_t)(m0+r)*KL + kk + c*4; \
        asm volatile("cp.async.cg.shared.global [%0], [%1], 16;"::"r"(dst),"l"(src)); \
    } \
    { int r = tid>>2, c = tid&3; \
      unsigned dst = (unsigned)__cvta_generic_to_shared(&Bs[bufi][r][c*4]); \
      const float* src = B + (size_t)(n0+r)*KL + kk + c*4; \
      asm volatile("cp.async.cg.shared.global [%0], [%1], 16;"::"r"(dst),"l"(src)); } \
    asm volatile("cp.async.commit_group;"); \
} while(0)

    STAGE(0, 0);
    const int KT = KL/16;
    for (int kt=0; kt<KT; ++kt){
        const int buf = kt&1;
        if (kt+1 < KT){ STAGE(buf^1, kt+1); asm volatile("cp.async.wait_group 1;"); }
        else          { asm volatile("cp.async.wait_group 0;"); }
        __syncthreads();
#pragma unroll
        for (int k8=0;k8<2;k8++){
            const int co = k8*8;
            unsigned a[2][4];
#pragma unroll
            for (int mi=0;mi<2;mi++){
                int rb = wm + mi*16 + lr;
                a[mi][0] = __float_as_uint(As[buf][rb  ][co+lc]);
                a[mi][1] = __float_as_uint(As[buf][rb+8][co+lc]);
                a[mi][2] = __float_as_uint(As[buf][rb  ][co+lc+4]);
                a[mi][3] = __float_as_uint(As[buf][rb+8][co+lc+4]);
            }
#pragma unroll
            for (int nj=0;nj<4;nj++){
                int nb = wn + nj*8 + lr;
                unsigned b0 = __float_as_uint(Bs[buf][nb][co+lc]);
                unsigned b1 = __float_as_uint(Bs[buf][nb][co+lc+4]);
#pragma unroll
                for (int mi=0;mi<2;mi++){
                    asm volatile(
                      "mma.sync.aligned.m16n8k8.row.col.f32.tf32.tf32.f32 "
                      "{%0,%1,%2,%3},{%4,%5,%6,%7},{%8,%9},{%0,%1,%2,%3};"
                      : "+f"(d[mi][nj][0]),"+f"(d[mi][nj][1]),"+f"(d[mi][nj][2]),"+f"(d[mi][nj][3])
                      : "r"(a[mi][0]),"r"(a[mi][1]),"r"(a[mi][2]),"r"(a[mi][3]),"r"(b0),"r"(b1));
                }
            }
        }
        __syncthreads();
    }
#undef STAGE

    // epilogue via smem (reuse As), coalesced float4 stores
    float* ep = &As[0][0][0] + w*640;
#pragma unroll
    for (int h=0; h<2; h++){
#pragma unroll
        for (int mi=0;mi<2;mi++){
#pragma unroll
            for (int njl=0;njl<2;njl++){
                int nj = h*2 + njl;
                int r0 = mi*16 + lr;
                ep[ r0   *20 + njl*8 + lc*2    ] = d[mi][nj][0];
                ep[ r0   *20 + njl*8 + lc*2 + 1] = d[mi][nj][1];
                ep[(r0+8)*20 + njl*8 + lc*2    ] = d[mi][nj][2];
                ep[(r0+8)*20 + njl*8 + lc*2 + 1] = d[mi][nj][3];
            }
        }
        __syncwarp();
#pragma unroll
        for (int q=0;q<4;q++){
            int idx = q*32 + lane;
            int r = idx>>2, c4 = idx&3;
            float4 vv = *reinterpret_cast<float4*>(&ep[r*20 + c4*4]);
            size_t nn = (size_t)n0 + wn + h*16 + c4*4;
            float4 bb = *reinterpret_cast<const float4*>(&bias[nn]);
            vv.x+=bb.x; vv.y+=bb.y; vv.z+=bb.z; vv.w+=bb.w;
            *reinterpret_cast<float4*>(&C[(size_t)(m0+wm+r)*VV + nn]) = vv;
        }
        __syncwarp();
    }
}

__global__ __launch_bounds__(512) void tail_kernel(float* __restrict__ out)
{
    int idx = blockIdx.x*blockDim.x + threadIdx.x;
    int part = idx / (BB*HH);
    int off  = idx % (BB*HH);
    int b = off / HH, u = off % HH;
    float val;
    if      (part == 0) val = g_xcat1[b*K1 + u];
    else if (part == 1) val = g_h1[off];
    else if (part == 2) val = g_c0[off];
    else                val = g_c1[off];
    out[OUT_TAIL_OFF + idx] = val;
}

extern "C" void kernel_launch(void* const* d_in, const int* in_sizes, int n_in,
                              void* d_out, int out_size)
{
    const float* enc  = (const float*)d_in[0];
    const int*   tok  = (const int*)  d_in[1];
    const float* emb  = (const float*)d_in[2];
    const float* Wq   = (const float*)d_in[3];
    const float* bq   = (const float*)d_in[4];
    const float* Wk   = (const float*)d_in[5];
    const float* bk   = (const float*)d_in[6];
    const float* v    = (const float*)d_in[7];
    const float* Wih0 = (const float*)d_in[8];
    const float* Whh0 = (const float*)d_in[9];
    const float* bih0 = (const float*)d_in[10];
    const float* bhh0 = (const float*)d_in[11];
    const float* Wih1 = (const float*)d_in[12];
    const float* Whh1 = (const float*)d_in[13];
    const float* bih1 = (const float*)d_in[14];
    const float* bhh1 = (const float*)d_in[15];
    const float* Wout = (const float*)d_in[16];
    const float* bout = (const float*)d_in[17];
    float* out = (float*)d_out;

    float *p_keyproj, *p_Wcat0, *p_Wcat1, *p_Wt32;
    float *p_xcat0, *p_xcat1, *p_part0, *p_part1, *p_Xall;
    cudaGetSymbolAddress((void**)&p_keyproj, g_keyproj);
    cudaGetSymbolAddress((void**)&p_Wcat0,  g_Wcat0);
    cudaGetSymbolAddress((void**)&p_Wcat1,  g_Wcat1);
    cudaGetSymbolAddress((void**)&p_Wt32,   g_Wt32);
    cudaGetSymbolAddress((void**)&p_xcat0,  g_xcat0);
    cudaGetSymbolAddress((void**)&p_xcat1,  g_xcat1);
    cudaGetSymbolAddress((void**)&p_part0,  g_part0);
    cudaGetSymbolAddress((void**)&p_part1,  g_part1);
    cudaGetSymbolAddress((void**)&p_Xall,   g_Xall);

    init_kernel<<<2048, 256>>>(Wih0, Whh0, bih0, bhh0, Wih1, Whh1, bih1, bhh1, Wq, bq);
    cvt_wout<<<2048, 256>>>(Wout);

    {   // key_proj = enc(8192x512) @ Wk^T + bk
        dim3 grid(HH/64, (BB*SS)/64);
        gemm_tn<64,64,16,4,4,256><<<grid, 256>>>(enc, Wk, bk, p_keyproj, BB*SS, HH, EENC);
    }

    for (int t = 0; t < TT; ++t){
        scores_kernel<<<dim3(BB, 8), 256>>>(v);
        smctx_kernel<<<BB, 256>>>(enc, tok, emb, t);
        gates_gemm<<<dim3(16, 10), 256>>>(p_xcat0, p_Wcat0, p_part0, K0);
        cell0_kernel<<<BB, 512>>>();
        gates_gemm<<<dim3(16, 8), 256>>>(p_xcat1, p_Wcat1, p_part1, K1);
        cell1_kernel<<<BB, 512>>>(bq, t);
    }

    {   // logits = Xall(4096x1024) @ Wt32^T + bout
        dim3 grid(VV/64, (BB*TT)/128);
        logits_mma<<<grid, 256>>>(p_Xall, p_Wt32, bout, out);
    }
    tail_kernel<<<128, 512>>>(out);
}

// round 4
// speedup vs baseline: 3.2100x; 1.4678x over previous
#include <cuda_runtime.h>
#include <cstdint>

#define BB 32
#define SS 256
#define TT 128
#define EENC 512
#define HH 512
#define EEMB 256
#define VV 32000
#define K0 1280
#define K1 1024
#define KL 1024
#define OUT_TAIL_OFF 131072000ll

__device__ float g_keyproj[BB*SS*HH];
__device__ float g_Wcat0[2048*K0];
__device__ float g_Wcat1[2048*K1];
__device__ float g_bcat0[2048];
__device__ float g_bcat1[2048];
__device__ float g_Wqt[HH*HH];
__device__ float g_Wt32[(size_t)VV*KL];
__device__ float g_xcat0[BB*K0];
__device__ float g_xcat1[BB*K1];
__device__ float g_part0[10*BB*2048];
__device__ float g_part1[8*BB*2048];
__device__ float g_h1[BB*HH];
__device__ float g_c0[BB*HH];
__device__ float g_c1[BB*HH];
__device__ float g_qp[BB*HH];
__device__ float g_scores[BB*SS];
__device__ float g_Xall[(size_t)BB*TT*KL];

// accurate tanh/sigmoid for the LSTM recurrence (error must stay tiny)
__device__ __forceinline__ float tanh_acc(float x){
    float xx = fminf(15.f, fmaxf(-15.f, x));
    float e  = __expf(2.f*xx);
    return 1.f - __fdividef(2.f, e + 1.f);
}
__device__ __forceinline__ float sigf(float x){
    float xx = fminf(30.f, fmaxf(-30.f, x));
    return __fdividef(1.f, 1.f + __expf(-xx));
}
// fast tanh for attention scores (4.2M/step; softmax tolerates ~1e-5)
__device__ __forceinline__ float tanh_fast(float x){
    float y; asm("tanh.approx.f32 %0, %1;" : "=f"(y) : "f"(x));
    return y;
}
__device__ __forceinline__ float tf32r(float x){
    unsigned u; asm("cvt.rna.tf32.f32 %0, %1;" : "=r"(u) : "f"(x));
    return __uint_as_float(u);
}

__global__ void init_kernel(const float* __restrict__ Wih0, const float* __restrict__ Whh0,
                            const float* __restrict__ bih0, const float* __restrict__ bhh0,
                            const float* __restrict__ Wih1, const float* __restrict__ Whh1,
                            const float* __restrict__ bih1, const float* __restrict__ bhh1,
                            const float* __restrict__ Wq,   const float* __restrict__ bq)
{
    const int NW0=2048*K0, NW1=2048*K1, NB=2048, NWQ=HH*HH, NQP=BB*HH;
    const int NZ = BB*HH*3 + BB*K0 + BB*K1;
    const int TOT = NW0+NW1+2*NB+NWQ+NQP+NZ;
    for (int idx = blockIdx.x*blockDim.x+threadIdx.x; idx < TOT; idx += gridDim.x*blockDim.x){
        int r = idx;
        if (r < NW0){ int j=r/K0,k=r%K0; g_Wcat0[r]=(k<768)?Wih0[j*768+k]:Whh0[j*512+(k-768)]; continue; }
        r -= NW0;
        if (r < NW1){ int j=r/K1,k=r%K1; g_Wcat1[r]=(k<512)?Wih1[j*512+k]:Whh1[j*512+(k-512)]; continue; }
        r -= NW1;
        if (r < NB){ g_bcat0[r]=bih0[r]+bhh0[r]; continue; }
        r -= NB;
        if (r < NB){ g_bcat1[r]=bih1[r]+bhh1[r]; continue; }
        r -= NB;
        if (r < NWQ){ int k=r/HH,h=r%HH; g_Wqt[r]=Wq[h*HH+k]; continue; }
        r -= NWQ;
        if (r < NQP){ g_qp[r]=bq[r%HH]; continue; }
        r -= NQP;
        if (r < BB*HH){ g_h1[r]=0.f; continue; }
        r -= BB*HH;
        if (r < BB*HH){ g_c0[r]=0.f; continue; }
        r -= BB*HH;
        if (r < BB*HH){ g_c1[r]=0.f; continue; }
        r -= BB*HH;
        if (r < BB*K0){ g_xcat0[r]=0.f; continue; }
        r -= BB*K0;
        g_xcat1[r]=0.f;
    }
}

__global__ void cvt_wout(const float* __restrict__ Wout)
{
    size_t n = (size_t)VV*KL/4;
    for (size_t i = blockIdx.x*blockDim.x+threadIdx.x; i < n; i += (size_t)gridDim.x*blockDim.x){
        float4 v = reinterpret_cast<const float4*>(Wout)[i];
        v.x=tf32r(v.x); v.y=tf32r(v.y); v.z=tf32r(v.z); v.w=tf32r(v.w);
        reinterpret_cast<float4*>(g_Wt32)[i] = v;
    }
}

// fp32 GEMM for keyproj: C = A@B^T + bias
template<int BM,int BN,int BK,int TM,int TN,int THREADS>
__global__ __launch_bounds__(THREADS) void gemm_tn(
    const float* __restrict__ A, const float* __restrict__ B,
    const float* __restrict__ bias, float* __restrict__ C, int M, int N, int K)
{
    constexpr int AF4 = BM*BK/(4*THREADS);
    constexpr int BF4 = BN*BK/(4*THREADS);
    constexpr int KC4 = BK/4;
    constexpr int NT  = BN/TN;
    __shared__ float As[2][BK][BM];
    __shared__ float Bs[2][BK][BN];
    const int tid = threadIdx.x;
    const int tm = (tid/NT)*TM, tn = (tid%NT)*TN;
    const size_t m0 = (size_t)blockIdx.y*BM, n0 = (size_t)blockIdx.x*BN;
    const float* Ab = A + m0*K;
    const float* Bb = B + n0*K;
    float acc[TM][TN];
#pragma unroll
    for (int i=0;i<TM;i++)
#pragma unroll
        for (int j=0;j<TN;j++) acc[i][j]=0.f;
    float4 ra[AF4], rb[BF4];
#pragma unroll
    for (int i=0;i<AF4;i++){ int f=tid+i*THREADS,r=f/KC4,c=f%KC4;
        ra[i]=*reinterpret_cast<const float4*>(Ab+(size_t)r*K+c*4); }
#pragma unroll
    for (int i=0;i<BF4;i++){ int f=tid+i*THREADS,r=f/KC4,c=f%KC4;
        rb[i]=*reinterpret_cast<const float4*>(Bb+(size_t)r*K+c*4); }
#pragma unroll
    for (int i=0;i<AF4;i++){ int f=tid+i*THREADS,r=f/KC4,c=f%KC4;
        As[0][c*4+0][r]=ra[i].x; As[0][c*4+1][r]=ra[i].y; As[0][c*4+2][r]=ra[i].z; As[0][c*4+3][r]=ra[i].w; }
#pragma unroll
    for (int i=0;i<BF4;i++){ int f=tid+i*THREADS,r=f/KC4,c=f%KC4;
        Bs[0][c*4+0][r]=rb[i].x; Bs[0][c*4+1][r]=rb[i].y; Bs[0][c*4+2][r]=rb[i].z; Bs[0][c*4+3][r]=rb[i].w; }
    __syncthreads();
    const int KT = K/BK;
    for (int kt=0; kt<KT; ++kt){
        const int cur = kt&1;
        const bool nx = (kt+1<KT);
        if (nx){
            const float* A2 = Ab+(size_t)(kt+1)*BK;
            const float* B2 = Bb+(size_t)(kt+1)*BK;
#pragma unroll
            for (int i=0;i<AF4;i++){ int f=tid+i*THREADS,r=f/KC4,c=f%KC4;
                ra[i]=*reinterpret_cast<const float4*>(A2+(size_t)r*K+c*4); }
#pragma unroll
            for (int i=0;i<BF4;i++){ int f=tid+i*THREADS,r=f/KC4,c=f%KC4;
                rb[i]=*reinterpret_cast<const float4*>(B2+(size_t)r*K+c*4); }
        }
#pragma unroll
        for (int k=0;k<BK;k++){
            float a[TM], b[TN];
#pragma unroll
            for (int i=0;i<TM/4;i++){ float4 t=*reinterpret_cast<const float4*>(&As[cur][k][tm+i*4]);
                a[i*4]=t.x;a[i*4+1]=t.y;a[i*4+2]=t.z;a[i*4+3]=t.w; }
#pragma unroll
            for (int j=0;j<TN/4;j++){ float4 t=*reinterpret_cast<const float4*>(&Bs[cur][k][tn+j*4]);
                b[j*4]=t.x;b[j*4+1]=t.y;b[j*4+2]=t.z;b[j*4+3]=t.w; }
#pragma unroll
            for (int i=0;i<TM;i++)
#pragma unroll
                for (int j=0;j<TN;j++) acc[i][j]=fmaf(a[i],b[j],acc[i][j]);
        }
        if (nx){
            const int nb = cur^1;
#pragma unroll
            for (int i=0;i<AF4;i++){ int f=tid+i*THREADS,r=f/KC4,c=f%KC4;
                As[nb][c*4+0][r]=ra[i].x; As[nb][c*4+1][r]=ra[i].y; As[nb][c*4+2][r]=ra[i].z; As[nb][c*4+3][r]=ra[i].w; }
#pragma unroll
            for (int i=0;i<BF4;i++){ int f=tid+i*THREADS,r=f/KC4,c=f%KC4;
                Bs[nb][c*4+0][r]=rb[i].x; Bs[nb][c*4+1][r]=rb[i].y; Bs[nb][c*4+2][r]=rb[i].z; Bs[nb][c*4+3][r]=rb[i].w; }
            __syncthreads();
        }
    }
#pragma unroll
    for (int i=0;i<TM;i++)
#pragma unroll
        for (int j=0;j<TN;j++){
            size_t cn = n0+tn+j;
            C[(m0+tm+i)*(size_t)N+cn] = acc[i][j] + bias[cn];
        }
}

// gates split-K: partials Cp[split][32][2048]
__global__ __launch_bounds__(256) void gates_gemm(
    const float* __restrict__ X, const float* __restrict__ W,
    float* __restrict__ Cp, int K)
{
    __shared__ float As[2][16][32];
    __shared__ float Bs[2][16][132];
    const int tid = threadIdx.x;
    const int j0 = blockIdx.x*128;
    const int k0 = blockIdx.y*128;
    const int tm = (tid>>5)*4, tn = (tid&31)*4;
    float acc[4][4] = {};
    float4 ra; float4 rb[2];
    if (tid < 128){ int r=tid>>2,c=tid&3;
        ra = *reinterpret_cast<const float4*>(X+(size_t)r*K+k0+c*4); }
#pragma unroll
    for (int i=0;i<2;i++){ int f=tid+i*256,r=f>>2,c=f&3;
        rb[i] = *reinterpret_cast<const float4*>(W+(size_t)(j0+r)*K+k0+c*4); }
    if (tid < 128){ int r=tid>>2,c=tid&3;
        As[0][c*4+0][r]=ra.x; As[0][c*4+1][r]=ra.y; As[0][c*4+2][r]=ra.z; As[0][c*4+3][r]=ra.w; }
#pragma unroll
    for (int i=0;i<2;i++){ int f=tid+i*256,r=f>>2,c=f&3;
        Bs[0][c*4+0][r]=rb[i].x; Bs[0][c*4+1][r]=rb[i].y; Bs[0][c*4+2][r]=rb[i].z; Bs[0][c*4+3][r]=rb[i].w; }
    __syncthreads();
    for (int kt=0; kt<8; ++kt){
        const int buf = kt&1;
        const bool nx = (kt<7);
        if (nx){
            int kk = k0 + (kt+1)*16;
            if (tid < 128){ int r=tid>>2,c=tid&3;
                ra = *reinterpret_cast<const float4*>(X+(size_t)r*K+kk+c*4); }
#pragma unroll
            for (int i=0;i<2;i++){ int f=tid+i*256,r=f>>2,c=f&3;
                rb[i] = *reinterpret_cast<const float4*>(W+(size_t)(j0+r)*K+kk+c*4); }
        }
#pragma unroll
        for (int k=0;k<16;k++){
            float4 a = *reinterpret_cast<const float4*>(&As[buf][k][tm]);
            float4 b = *reinterpret_cast<const float4*>(&Bs[buf][k][tn]);
            float av[4]={a.x,a.y,a.z,a.w}, bv[4]={b.x,b.y,b.z,b.w};
#pragma unroll
            for (int i=0;i<4;i++)
#pragma unroll
                for (int j=0;j<4;j++) acc[i][j]=fmaf(av[i],bv[j],acc[i][j]);
        }
        if (nx){
            const int nb = buf^1;
            if (tid < 128){ int r=tid>>2,c=tid&3;
                As[nb][c*4+0][r]=ra.x; As[nb][c*4+1][r]=ra.y; As[nb][c*4+2][r]=ra.z; As[nb][c*4+3][r]=ra.w; }
#pragma unroll
            for (int i=0;i<2;i++){ int f=tid+i*256,r=f>>2,c=f&3;
                Bs[nb][c*4+0][r]=rb[i].x; Bs[nb][c*4+1][r]=rb[i].y; Bs[nb][c*4+2][r]=rb[i].z; Bs[nb][c*4+3][r]=rb[i].w; }
            __syncthreads();
        }
    }
    float* out = Cp + blockIdx.y*65536;
#pragma unroll
    for (int i=0;i<4;i++)
#pragma unroll
        for (int j=0;j<4;j++)
            out[(tm+i)*2048 + j0+tn+j] = acc[i][j];
}

__global__ __launch_bounds__(512) void cell0_kernel()
{
    const int b = blockIdx.x, u = threadIdx.x;
    float gi=g_bcat0[u], gf=g_bcat0[512+u], gg=g_bcat0[1024+u], go=g_bcat0[1536+u];
#pragma unroll
    for (int s=0;s<10;s++){
        const float* p = g_part0 + s*65536 + b*2048;
        gi += p[u]; gf += p[512+u]; gg += p[1024+u]; go += p[1536+u];
    }
    float c = sigf(gf)*g_c0[b*HH+u] + sigf(gi)*tanh_acc(gg);
    float h = sigf(go)*tanh_acc(c);
    g_c0[b*HH+u] = c;
    g_xcat0[b*K0 + 768 + u] = h;
    g_xcat1[b*K1 + u]       = h;
}

__global__ __launch_bounds__(512) void cell1_kernel(const float* __restrict__ bq, int t)
{
    const int b = blockIdx.x, u = threadIdx.x;
    __shared__ float h1s[512];
    __shared__ float qpart[4][512];
    float gi=g_bcat1[u], gf=g_bcat1[512+u], gg=g_bcat1[1024+u], go=g_bcat1[1536+u];
#pragma unroll
    for (int s=0;s<8;s++){
        const float* p = g_part1 + s*65536 + b*2048;
        gi += p[u]; gf += p[512+u]; gg += p[1024+u]; go += p[1536+u];
    }
    float c = sigf(gf)*g_c1[b*HH+u] + sigf(gi)*tanh_acc(gg);
    float h = sigf(go)*tanh_acc(c);
    g_c1[b*HH+u] = c;
    g_h1[b*HH+u] = h;
    g_xcat1[b*K1 + 512 + u] = h;
    g_Xall[((size_t)(b*TT+t))*KL + u] = tf32r(h);
    h1s[u] = h;
    __syncthreads();
    // qproj for next step: qp = Wq@h1 + bq, Wqt is [k][h]
    const int h4 = (u & 127)*4, kp = u >> 7;
    float4 a = make_float4(0.f,0.f,0.f,0.f);
    const float* wb = g_Wqt + (size_t)kp*128*HH + h4;
#pragma unroll 4
    for (int k=0;k<128;k++){
        float4 w4 = *reinterpret_cast<const float4*>(wb + (size_t)k*HH);
        float xv = h1s[kp*128 + k];
        a.x=fmaf(w4.x,xv,a.x); a.y=fmaf(w4.y,xv,a.y); a.z=fmaf(w4.z,xv,a.z); a.w=fmaf(w4.w,xv,a.w);
    }
    *reinterpret_cast<float4*>(&qpart[kp][h4]) = a;
    __syncthreads();
    g_qp[b*HH+u] = qpart[0][u]+qpart[1][u]+qpart[2][u]+qpart[3][u] + bq[u];
}

// scores: one warp per (b, s); grid (32, 32), 8 warps/block
__global__ __launch_bounds__(256) void scores_kernel(const float* __restrict__ v)
{
    const int b = blockIdx.x, tid = threadIdx.x;
    const int w = tid>>5, lane = tid&31;
    __shared__ float qs[512], vsm[512];
    qs[tid]      = g_qp[b*HH+tid];
    qs[tid+256]  = g_qp[b*HH+tid+256];
    vsm[tid]     = v[tid];
    vsm[tid+256] = v[tid+256];
    __syncthreads();
    const int s = blockIdx.y*8 + w;
    const float* kp = g_keyproj + ((size_t)(b*SS+s))*HH;
    float acc = 0.f;
#pragma unroll
    for (int i=0;i<4;i++){
        int h = i*128 + lane*4;
        float4 k4 = *reinterpret_cast<const float4*>(kp + h);
        float4 q4 = *reinterpret_cast<const float4*>(&qs[h]);
        float4 v4 = *reinterpret_cast<const float4*>(&vsm[h]);
        acc = fmaf(v4.x, tanh_fast(k4.x+q4.x), acc);
        acc = fmaf(v4.y, tanh_fast(k4.y+q4.y), acc);
        acc = fmaf(v4.z, tanh_fast(k4.z+q4.z), acc);
        acc = fmaf(v4.w, tanh_fast(k4.w+q4.w), acc);
    }
#pragma unroll
    for (int o=16;o;o>>=1) acc += __shfl_xor_sync(0xffffffffu, acc, o);
    if (lane == 0) g_scores[b*SS+s] = acc;
}

// softmax (redundant per block) + context chunk + emb gather; grid (32, 4)
__global__ __launch_bounds__(256) void smctx_kernel(
    const float* __restrict__ enc, const int* __restrict__ tok,
    const float* __restrict__ emb, int t)
{
    const int b = blockIdx.x, chunk = blockIdx.y, tid = threadIdx.x;
    const int w = tid>>5, lane = tid&31;
    __shared__ float wsm[SS];
    __shared__ float red[8];
    __shared__ float smax_s, sinv_s;
    __shared__ float cpart[2][128];
    float x = g_scores[b*SS+tid];
    float m = x;
#pragma unroll
    for (int o=16;o;o>>=1) m = fmaxf(m, __shfl_xor_sync(0xffffffffu, m, o));
    if (lane==0) red[w]=m;
    __syncthreads();
    if (tid==0){ float mm=red[0];
#pragma unroll
        for (int i=1;i<8;i++) mm=fmaxf(mm,red[i]); smax_s=mm; }
    __syncthreads();
    float ex = __expf(x - smax_s);
    float s2 = ex;
#pragma unroll
    for (int o=16;o;o>>=1) s2 += __shfl_xor_sync(0xffffffffu, s2, o);
    if (lane==0) red[w]=s2;
    __syncthreads();
    if (tid==0){ float ss=0.f;
#pragma unroll
        for (int i=0;i<8;i++) ss+=red[i]; sinv_s=1.f/ss; }
    __syncthreads();
    wsm[tid] = ex*sinv_s;
    if (chunk == 0){
        int row = tok[b*TT+t];
        g_xcat0[b*K0+tid] = emb[(size_t)row*EEMB+tid];
    }
    __syncthreads();
    // context: this block covers e in [chunk*128, chunk*128+128); s split in halves
    const int el = tid & 127, half = tid >> 7;
    const int e = chunk*128 + el;
    const float* eb = enc + ((size_t)b*SS + half*128)*EENC + e;
    float acc = 0.f;
#pragma unroll 4
    for (int s=0;s<128;s++) acc = fmaf(wsm[half*128+s], eb[(size_t)s*EENC], acc);
    cpart[half][el] = acc;
    __syncthreads();
    if (tid < 128){
        float ctx = cpart[0][tid] + cpart[1][tid];
        g_xcat0[b*K0 + 256 + e] = ctx;
        g_Xall[((size_t)(b*TT+t))*KL + 512 + e] = tf32r(ctx);
    }
}

// logits: tf32 mma.sync, BM128 x BN128 x BK16, 8 warps; grid (M/128, N/128) m-major
__global__ __launch_bounds__(256) void logits_mma(
    const float* __restrict__ A, const float* __restrict__ B,
    const float* __restrict__ bias, float* __restrict__ C)
{
    __shared__ float As[2][128][20];
    __shared__ float Bs[2][128][20];
    const int tid = threadIdx.x, lane = tid&31, w = tid>>5;
    const int wm = (w&3)*32, wn = (w>>2)*64;
    const int m0 = blockIdx.x*128, n0 = blockIdx.y*128;
    const int lr = lane>>2, lc = lane&3;
    float d[2][8][4] = {};

#define STAGE(bufi, kt) do { \
    int kk = (kt)*16; \
    _Pragma("unroll") \
    for (int i=0;i<2;i++){ \
        int f = tid + i*256; int r = f>>2, c = f&3; \
        unsigned dst = (unsigned)__cvta_generic_to_shared(&As[bufi][r][c*4]); \
        const float* src = A + (size_t)(m0+r)*KL + kk + c*4; \
        asm volatile("cp.async.cg.shared.global [%0], [%1], 16;"::"r"(dst),"l"(src)); \
    } \
    _Pragma("unroll") \
    for (int i=0;i<2;i++){ \
        int f = tid + i*256; int r = f>>2, c = f&3; \
        unsigned dst = (unsigned)__cvta_generic_to_shared(&Bs[bufi][r][c*4]); \
        const float* src = B + (size_t)(n0+r)*KL + kk + c*4; \
        asm volatile("cp.async.cg.shared.global [%0], [%1], 16;"::"r"(dst),"l"(src)); \
    } \
    asm volatile("cp.async.commit_group;"); \
} while(0)

    STAGE(0, 0);
    const int KT = KL/16;
    for (int kt=0; kt<KT; ++kt){
        const int buf = kt&1;
        if (kt+1 < KT){ STAGE(buf^1, kt+1); asm volatile("cp.async.wait_group 1;"); }
        else          { asm volatile("cp.async.wait_group 0;"); }
        __syncthreads();
#pragma unroll
        for (int k8=0;k8<2;k8++){
            const int co = k8*8;
            unsigned a[2][4];
#pragma unroll
            for (int mi=0;mi<2;mi++){
                int rb = wm + mi*16 + lr;
                a[mi][0] = __float_as_uint(As[buf][rb  ][co+lc]);
                a[mi][1] = __float_as_uint(As[buf][rb+8][co+lc]);
                a[mi][2] = __float_as_uint(As[buf][rb  ][co+lc+4]);
                a[mi][3] = __float_as_uint(As[buf][rb+8][co+lc+4]);
            }
#pragma unroll
            for (int nj=0;nj<8;nj++){
                int nb = wn + nj*8 + lr;
                unsigned b0 = __float_as_uint(Bs[buf][nb][co+lc]);
                unsigned b1 = __float_as_uint(Bs[buf][nb][co+lc+4]);
#pragma unroll
                for (int mi=0;mi<2;mi++){
                    asm volatile(
                      "mma.sync.aligned.m16n8k8.row.col.f32.tf32.tf32.f32 "
                      "{%0,%1,%2,%3},{%4,%5,%6,%7},{%8,%9},{%0,%1,%2,%3};"
                      : "+f"(d[mi][nj][0]),"+f"(d[mi][nj][1]),"+f"(d[mi][nj][2]),"+f"(d[mi][nj][3])
                      : "r"(a[mi][0]),"r"(a[mi][1]),"r"(a[mi][2]),"r"(a[mi][3]),"r"(b0),"r"(b1));
                }
            }
        }
        __syncthreads();
    }
#undef STAGE

    // epilogue via smem (reuse As), coalesced float4 stores; 4 chunks of 16 cols
    float* ep = &As[0][0][0] + w*640;
#pragma unroll
    for (int h=0; h<4; h++){
#pragma unroll
        for (int mi=0;mi<2;mi++){
#pragma unroll
            for (int njl=0;njl<2;njl++){
                int nj = h*2 + njl;
                int r0 = mi*16 + lr;
                ep[ r0   *20 + njl*8 + lc*2    ] = d[mi][nj][0];
                ep[ r0   *20 + njl*8 + lc*2 + 1] = d[mi][nj][1];
                ep[(r0+8)*20 + njl*8 + lc*2    ] = d[mi][nj][2];
                ep[(r0+8)*20 + njl*8 + lc*2 + 1] = d[mi][nj][3];
            }
        }
        __syncwarp();
#pragma unroll
        for (int q=0;q<4;q++){
            int idx = q*32 + lane;
            int r = idx>>2, c4 = idx&3;
            float4 vv = *reinterpret_cast<float4*>(&ep[r*20 + c4*4]);
            size_t nn = (size_t)n0 + wn + h*16 + c4*4;
            float4 bb = *reinterpret_cast<const float4*>(&bias[nn]);
            vv.x+=bb.x; vv.y+=bb.y; vv.z+=bb.z; vv.w+=bb.w;
            *reinterpret_cast<float4*>(&C[(size_t)(m0+wm+r)*VV + nn]) = vv;
        }
        __syncwarp();
    }
}

__global__ __launch_bounds__(512) void tail_kernel(float* __restrict__ out)
{
    int idx = blockIdx.x*blockDim.x + threadIdx.x;
    int part = idx / (BB*HH);
    int off  = idx % (BB*HH);
    int b = off / HH, u = off % HH;
    float val;
    if      (part == 0) val = g_xcat1[b*K1 + u];
    else if (part == 1) val = g_h1[off];
    else if (part == 2) val = g_c0[off];
    else                val = g_c1[off];
    out[OUT_TAIL_OFF + idx] = val;
}

extern "C" void kernel_launch(void* const* d_in, const int* in_sizes, int n_in,
                              void* d_out, int out_size)
{
    const float* enc  = (const float*)d_in[0];
    const int*   tok  = (const int*)  d_in[1];
    const float* emb  = (const float*)d_in[2];
    const float* Wq   = (const float*)d_in[3];
    const float* bq   = (const float*)d_in[4];
    const float* Wk   = (const float*)d_in[5];
    const float* bk   = (const float*)d_in[6];
    const float* v    = (const float*)d_in[7];
    const float* Wih0 = (const float*)d_in[8];
    const float* Whh0 = (const float*)d_in[9];
    const float* bih0 = (const float*)d_in[10];
    const float* bhh0 = (const float*)d_in[11];
    const float* Wih1 = (const float*)d_in[12];
    const float* Whh1 = (const float*)d_in[13];
    const float* bih1 = (const float*)d_in[14];
    const float* bhh1 = (const float*)d_in[15];
    const float* Wout = (const float*)d_in[16];
    const float* bout = (const float*)d_in[17];
    float* out = (float*)d_out;

    float *p_keyproj, *p_Wcat0, *p_Wcat1, *p_Wt32;
    float *p_xcat0, *p_xcat1, *p_part0, *p_part1, *p_Xall;
    cudaGetSymbolAddress((void**)&p_keyproj, g_keyproj);
    cudaGetSymbolAddress((void**)&p_Wcat0,  g_Wcat0);
    cudaGetSymbolAddress((void**)&p_Wcat1,  g_Wcat1);
    cudaGetSymbolAddress((void**)&p_Wt32,   g_Wt32);
    cudaGetSymbolAddress((void**)&p_xcat0,  g_xcat0);
    cudaGetSymbolAddress((void**)&p_xcat1,  g_xcat1);
    cudaGetSymbolAddress((void**)&p_part0,  g_part0);
    cudaGetSymbolAddress((void**)&p_part1,  g_part1);
    cudaGetSymbolAddress((void**)&p_Xall,   g_Xall);

    init_kernel<<<2048, 256>>>(Wih0, Whh0, bih0, bhh0, Wih1, Whh1, bih1, bhh1, Wq, bq);
    cvt_wout<<<2048, 256>>>(Wout);

    {   // key_proj = enc(8192x512) @ Wk^T + bk
        dim3 grid(HH/64, (BB*SS)/64);
        gemm_tn<64,64,16,4,4,256><<<grid, 256>>>(enc, Wk, bk, p_keyproj, BB*SS, HH, EENC);
    }

    for (int t = 0; t < TT; ++t){
        scores_kernel<<<dim3(BB, 32), 256>>>(v);
        smctx_kernel<<<dim3(BB, 4), 256>>>(enc, tok, emb, t);
        gates_gemm<<<dim3(16, 10), 256>>>(p_xcat0, p_Wcat0, p_part0, K0);
        cell0_kernel<<<BB, 512>>>();
        gates_gemm<<<dim3(16, 8), 256>>>(p_xcat1, p_Wcat1, p_part1, K1);
        cell1_kernel<<<BB, 512>>>(bq, t);
    }

    {   // logits = Xall(4096x1024) @ Wt32^T + bout  (m-major grid for B-tile reuse)
        dim3 grid((BB*TT)/128, VV/128);
        logits_mma<<<grid, 256>>>(p_Xall, p_Wt32, bout, out);
    }
    tail_kernel<<<128, 512>>>(out);
}